// round 4
// baseline (speedup 1.0000x reference)
#include <cuda_runtime.h>
#include <cuda_fp16.h>
#include <cstdint>
#include <cstddef>

#define D1    200
#define NENT  100000
#define BATCH 1024
#define NREL  11
#define KDIM  80   // DS+DA+DO = 30+30+20

__constant__ int c_perm[NREL] = {8, 0, 3, 9, 4, 5, 6, 7, 1, 10, 2};

// Scratch (device globals: no allocations allowed)
__device__ float g_M[NREL * D1 * D1];            // 11 relation matrices
__device__ float g_x[BATCH * D1];                // gathered entities (raw)
__device__ float g_y[BATCH * D1];                // after W*x (pre-BN1)
__device__ __align__(16) __half g_yh[BATCH * D1];  // BN1(y) in fp16
__device__ __align__(16) __half g_Eh[NENT * D1];   // E in fp16 (40 MB)
__device__ float g_m0[D1], g_r0[D1], g_m1[D1], g_r1[D1];
__device__ int   g_rel[BATCH];

// ===========================================================================
// helpers
// ===========================================================================
__device__ __forceinline__ uint32_t smem_u32(const void* p) {
    uint32_t a;
    asm("{ .reg .u64 t; cvta.to.shared.u64 t, %1; cvt.u32.u64 %0, t; }"
        : "=r"(a) : "l"(p));
    return a;
}
__device__ __forceinline__ void ldsm4(uint32_t& r0, uint32_t& r1, uint32_t& r2,
                                      uint32_t& r3, uint32_t addr) {
    asm volatile("ldmatrix.sync.aligned.m8n8.x4.shared.b16 {%0,%1,%2,%3}, [%4];"
        : "=r"(r0), "=r"(r1), "=r"(r2), "=r"(r3) : "r"(addr));
}
__device__ __forceinline__ void mma16816(float* d, const uint32_t* a, const uint32_t* b) {
    asm volatile(
        "mma.sync.aligned.m16n8k16.row.col.f32.f16.f16.f32 "
        "{%0,%1,%2,%3}, {%4,%5,%6,%7}, {%8,%9}, {%0,%1,%2,%3};\n"
        : "+f"(d[0]), "+f"(d[1]), "+f"(d[2]), "+f"(d[3])
        : "r"(a[0]), "r"(a[1]), "r"(a[2]), "r"(a[3]), "r"(b[0]), "r"(b[1]));
}
__device__ __forceinline__ float sigf(float x) {
    return __fdividef(1.f, 1.f + __expf(-x));
}

// ===========================================================================
// K1: build M[rel][j][k] = sum_i R[rel,i] * W_i(j,k) (closed-form indices)
// ===========================================================================
__global__ void k_build_M(const float* __restrict__ R1, const float* __restrict__ R2,
                          const float* __restrict__ R3, const float* __restrict__ W1,
                          const float* __restrict__ W2, const float* __restrict__ W3) {
    __shared__ float Rs[NREL * KDIM];
    for (int t = threadIdx.x; t < NREL * KDIM; t += blockDim.x) {
        int rel = t / KDIM, c = t % KDIM;
        float v = 0.f;
        if (rel < 3)      { if (c < 30) v = R1[rel * 30 + c]; }
        else if (rel < 8) { if (c >= 30 && c < 60) v = R2[(rel - 3) * 30 + (c - 30)]; }
        else              { v = R3[(rel - 8) * KDIM + c]; }
        Rs[t] = v;
    }
    __syncthreads();

    int idx = blockIdx.x * blockDim.x + threadIdx.x;
    if (idx >= D1 * D1) return;
    int j = idx / D1, k = idx % D1;
    int p = min(j, k), q = max(j, k);

    float acc[NREL];
#pragma unroll
    for (int r = 0; r < NREL; r++) acc[r] = 0.f;

    int s = p * (2 * D1 - p + 1) / 2 + (q - p);
    for (int i = 0; i < 30; i++) {
        float w = W1[i * (D1 * (D1 + 1) / 2) + s];
#pragma unroll
        for (int r = 0; r < NREL; r++) acc[r] += Rs[r * KDIM + i] * w;
    }
    if (j != k) {
        int u = p * (2 * D1 - p - 1) / 2 + (q - p - 1);
        float sgn = (k > j) ? 1.f : -1.f;
        for (int i = 0; i < 30; i++) {
            float w = sgn * W2[i * (D1 * (D1 - 1) / 2) + u];
#pragma unroll
            for (int r = 0; r < NREL; r++) acc[r] += Rs[r * KDIM + 30 + i] * w;
        }
    }
    for (int i = 0; i < 20; i++) {
        float w = W3[i * D1 * D1 + idx];
#pragma unroll
        for (int r = 0; r < NREL; r++) acc[r] += Rs[r * KDIM + 60 + i] * w;
    }
#pragma unroll
    for (int r = 0; r < NREL; r++) g_M[r * D1 * D1 + idx] = acc[r];
}

// ===========================================================================
// K2: gather E rows + resolve permuted relation ids
// ===========================================================================
__global__ void k_gather(const float* __restrict__ E, const int* __restrict__ e1,
                         const int* __restrict__ ridx) {
    int i = blockIdx.x * blockDim.x + threadIdx.x;
    if (i < BATCH) g_rel[i] = c_perm[ridx[i]];
    for (int t = i; t < BATCH * D1; t += gridDim.x * blockDim.x) {
        int b = t / D1, d = t % D1;
        g_x[t] = E[e1[b] * D1 + d];
    }
}

// ===========================================================================
// K2b: convert E to fp16 (each thread: 8 floats -> 8 halves)
// ===========================================================================
__global__ void k_cvtE(const float* __restrict__ E) {
    int t = blockIdx.x * blockDim.x + threadIdx.x;
    if (t >= NENT * D1 / 8) return;
    size_t base = (size_t)t * 8;
    float4 v0 = *(const float4*)&E[base];
    float4 v1 = *(const float4*)&E[base + 4];
    __half2 h0 = __floats2half2_rn(v0.x, v0.y);
    __half2 h1 = __floats2half2_rn(v0.z, v0.w);
    __half2 h2 = __floats2half2_rn(v1.x, v1.y);
    __half2 h3 = __floats2half2_rn(v1.z, v1.w);
    uint4 o;
    o.x = *(uint32_t*)&h0; o.y = *(uint32_t*)&h1;
    o.z = *(uint32_t*)&h2; o.w = *(uint32_t*)&h3;
    *(uint4*)&g_Eh[base] = o;
}

// ===========================================================================
// K3: per-feature batch stats (biased var, eps=1e-5)
// ===========================================================================
__global__ void k_stats(int which) {
    const float* src = which ? g_y : g_x;
    int d = blockIdx.x;
    __shared__ float sh[16], sh2[16];
    float s = 0.f, s2 = 0.f;
    for (int b = threadIdx.x; b < BATCH; b += blockDim.x) {
        float v = src[b * D1 + d];
        s += v; s2 += v * v;
    }
#pragma unroll
    for (int o = 16; o; o >>= 1) {
        s  += __shfl_down_sync(0xFFFFFFFFu, s,  o);
        s2 += __shfl_down_sync(0xFFFFFFFFu, s2, o);
    }
    int w = threadIdx.x >> 5, l = threadIdx.x & 31;
    if (l == 0) { sh[w] = s; sh2[w] = s2; }
    __syncthreads();
    if (threadIdx.x == 0) {
        float a = 0.f, b2 = 0.f;
        int nw = blockDim.x >> 5;
        for (int i = 0; i < nw; i++) { a += sh[i]; b2 += sh2[i]; }
        float m   = a  * (1.f / BATCH);
        float var = b2 * (1.f / BATCH) - m * m;
        if (which) { g_m1[d] = m; g_r1[d] = rsqrtf(var + 1e-5f); }
        else       { g_m0[d] = m; g_r0[d] = rsqrtf(var + 1e-5f); }
    }
}

// ===========================================================================
// K4: y[b,k] = sum_j M[rel_b][j][k] * BN0(x)[b,j]
// ===========================================================================
__global__ void k_wx(const float* __restrict__ g0, const float* __restrict__ b0) {
    int b = blockIdx.x;
    __shared__ float xs[D1];
    for (int d = threadIdx.x; d < D1; d += blockDim.x)
        xs[d] = (g_x[b * D1 + d] - g_m0[d]) * g_r0[d] * g0[d] + b0[d];
    __syncthreads();
    int k = threadIdx.x;
    if (k < D1) {
        const float* Mp = g_M + g_rel[b] * D1 * D1 + k;
        float a0 = 0.f, a1 = 0.f, a2 = 0.f, a3 = 0.f;
#pragma unroll 4
        for (int j = 0; j < D1; j += 4) {
            a0 += Mp[(j + 0) * D1] * xs[j + 0];
            a1 += Mp[(j + 1) * D1] * xs[j + 1];
            a2 += Mp[(j + 2) * D1] * xs[j + 2];
            a3 += Mp[(j + 3) * D1] * xs[j + 3];
        }
        g_y[b * D1 + k] = (a0 + a1) + (a2 + a3);
    }
}

// ===========================================================================
// K5: BN1 normalize -> fp16
// ===========================================================================
__global__ void k_norm1(const float* __restrict__ g1, const float* __restrict__ b1) {
    int t = blockIdx.x * blockDim.x + threadIdx.x;
    if (t < BATCH * D1) {
        int d = t % D1;
        float v = (g_y[t] - g_m1[d]) * g_r1[d] * g1[d] + b1[d];
        g_yh[t] = __float2half_rn(v);
    }
}

// ===========================================================================
// K6: scores = sigmoid(yh @ Eh^T) — fp16 mma.sync m16n8k16, fp32 accumulate
//   BM=128, BN=128, full K in smem (200 padded to 208), ldmatrix operands.
//   8 warps, each computing a 64x32 output tile. 2 CTAs/SM.
// ===========================================================================
#define GBM 128
#define GBN 128
#define KP  208        // 13 * 16
#define LDK 216        // smem row stride in halves (432 B, conflict-free)
#define NSTEP 13
#define SMEM_GEMM (2 * GBM * LDK * 2)   // A + B = 110592 B

__global__ __launch_bounds__(256, 2)
void k_gemm(float* __restrict__ out) {
    extern __shared__ char smem[];
    __half* sA = (__half*)smem;
    __half* sB = (__half*)smem + GBM * LDK;
    uint32_t sa = smem_u32(smem);
    uint32_t sb = sa + GBM * LDK * 2;

    int tid = threadIdx.x, lane = tid & 31, warp = tid >> 5;
    int bm0 = blockIdx.x * GBM;
    int bn0 = blockIdx.y * GBN;

    // ---- load A (g_yh) and B (g_Eh) tiles, zero-pad K to 208 ----
    for (int idx = tid; idx < GBM * 26; idx += 256) {
        int row = idx / 26, j = idx % 26;
        uint4 v = make_uint4(0, 0, 0, 0);
        if (j < 25) v = *(const uint4*)&g_yh[(bm0 + row) * D1 + j * 8];
        *(uint4*)&sA[row * LDK + j * 8] = v;
    }
    for (int idx = tid; idx < GBN * 26; idx += 256) {
        int row = idx / 26, j = idx % 26;
        int n = bn0 + row;
        uint4 v = make_uint4(0, 0, 0, 0);
        if (n < NENT && j < 25) v = *(const uint4*)&g_Eh[(size_t)n * D1 + j * 8];
        *(uint4*)&sB[row * LDK + j * 8] = v;
    }
    __syncthreads();

    // warp tile: 64 (M) x 32 (N);  wm in {0,1}, wn in {0..3}
    int wm = warp >> 2, wn = warp & 3;
    int tile = lane >> 3, r = lane & 7;

    // ldmatrix lane addresses (bytes)
    uint32_t aAddr[4], bAddr[2];
#pragma unroll
    for (int im = 0; im < 4; im++) {
        int rowA = wm * 64 + im * 16 + (tile & 1) * 8 + r;
        int kcol = (tile >> 1) * 8;
        aAddr[im] = sa + (rowA * LDK + kcol) * 2;
    }
#pragma unroll
    for (int i2 = 0; i2 < 2; i2++) {
        int rowB = wn * 32 + i2 * 16 + (tile >> 1) * 8 + r;
        int kcol = (tile & 1) * 8;
        bAddr[i2] = sb + (rowB * LDK + kcol) * 2;
    }

    float acc[4][4][4];
#pragma unroll
    for (int im = 0; im < 4; im++)
#pragma unroll
        for (int in_ = 0; in_ < 4; in_++)
#pragma unroll
            for (int c = 0; c < 4; c++) acc[im][in_][c] = 0.f;

    for (int step = 0; step < NSTEP; step++) {
        uint32_t af[4][4], bf[4][2];
#pragma unroll
        for (int im = 0; im < 4; im++) {
            ldsm4(af[im][0], af[im][1], af[im][2], af[im][3], aAddr[im]);
            aAddr[im] += 32;   // 16 halves along k
        }
#pragma unroll
        for (int i2 = 0; i2 < 2; i2++) {
            ldsm4(bf[2 * i2][0], bf[2 * i2][1], bf[2 * i2 + 1][0], bf[2 * i2 + 1][1],
                  bAddr[i2]);
            bAddr[i2] += 32;
        }
#pragma unroll
        for (int im = 0; im < 4; im++)
#pragma unroll
            for (int in_ = 0; in_ < 4; in_++)
                mma16816(acc[im][in_], af[im], bf[in_]);
    }

    // ---- epilogue: sigmoid + float2 stores ----
    int g = lane >> 2, tg = lane & 3;
#pragma unroll
    for (int im = 0; im < 4; im++) {
        int row0 = bm0 + wm * 64 + im * 16 + g;
#pragma unroll
        for (int in_ = 0; in_ < 4; in_++) {
            int col = bn0 + wn * 32 + in_ * 8 + tg * 2;
            if (col < NENT) {
                float2 v0 = make_float2(sigf(acc[im][in_][0]), sigf(acc[im][in_][1]));
                float2 v1 = make_float2(sigf(acc[im][in_][2]), sigf(acc[im][in_][3]));
                *(float2*)&out[(size_t)row0 * NENT + col]       = v0;
                *(float2*)&out[(size_t)(row0 + 8) * NENT + col] = v1;
            }
        }
    }
}

// ===========================================================================
extern "C" void kernel_launch(void* const* d_in, const int* in_sizes, int n_in,
                              void* d_out, int out_size) {
    const float* E    = (const float*)d_in[0];
    const float* R1   = (const float*)d_in[1];
    const float* R2   = (const float*)d_in[2];
    const float* R3   = (const float*)d_in[3];
    const float* W1   = (const float*)d_in[4];
    const float* W2   = (const float*)d_in[5];
    const float* W3   = (const float*)d_in[6];
    const float* g0   = (const float*)d_in[7];
    const float* b0   = (const float*)d_in[8];
    const float* g1   = (const float*)d_in[9];
    const float* b1   = (const float*)d_in[10];
    const int*   e1   = (const int*)d_in[11];
    const int*   ridx = (const int*)d_in[12];
    float* out = (float*)d_out;

    static int smem_set = 0;
    if (!smem_set) {
        cudaFuncSetAttribute(k_gemm, cudaFuncAttributeMaxDynamicSharedMemorySize,
                             SMEM_GEMM);
        smem_set = 1;
    }

    k_build_M<<<(D1 * D1 + 255) / 256, 256>>>(R1, R2, R3, W1, W2, W3);
    k_cvtE<<<(NENT * D1 / 8 + 255) / 256, 256>>>(E);
    k_gather<<<(BATCH * D1) / 256, 256>>>(E, e1, ridx);
    k_stats<<<D1, 256>>>(0);
    k_wx<<<BATCH, 256>>>(g0, b0);
    k_stats<<<D1, 256>>>(1);
    k_norm1<<<(BATCH * D1 + 255) / 256, 256>>>(g1, b1);

    dim3 grid(BATCH / GBM, (NENT + GBN - 1) / GBN);  // (8, 782), M fast
    k_gemm<<<grid, 256, SMEM_GEMM>>>(out);
}